// round 2
// baseline (speedup 1.0000x reference)
#include <cuda_runtime.h>
#include <cuda_bf16.h>
#include <math.h>

// ---------------------------------------------------------------------------
// LINKX forward, fp32 SIMT baseline.
// Pipeline (all on default stream, graph-capturable):
//   zero      : g_agg = 0, g_deg = 0
//   scatter   : per edge e: g_agg[dst] += adj_embed[src] (vector atomics), g_deg[dst]+=1
//   finalize  : g_agg[m] /= max(deg[m],1)                  -> ha_raw in place
//   G1 gemm   : g_hid = relu(x @ wx1 + bx1)            K=256, EPI_RELU
//   G2 gemm   : g_cat[:,0:128]   = g_hid @ wx2 + bx2   K=128, EPI_NONE   (= hx)
//   G3 gemm   : g_hid = relu(g_agg @ wa1 + ba1)        K=128, EPI_RELU
//   G4 gemm   : g_cat[:,128:256] = g_hid @ wa2 + ba2   K=128, EPI_NONE   (= ha)
//   G5 gemm   : g_hid = relu(relu(g_cat @ ww1 + bw1) + hx + ha)  K=256, EPI_LINKX
//   G6 gemm   : out = g_hid @ wc + bc                  (N=40 kernel)
// ---------------------------------------------------------------------------

#define NMAX   100000
#define HID    128
#define INDIM  256

// Scratch (static device globals: the sanctioned no-alloc workaround)
__device__ float g_agg[(size_t)NMAX * HID];     // aggregation / ha_raw
__device__ float g_deg[NMAX];
__device__ float g_hid[(size_t)NMAX * HID];     // hidden / h buffer (reused)
__device__ float g_cat[(size_t)NMAX * 2 * HID]; // [hx | ha] concatenated, ld=256

// ---------------------------------------------------------------------------
__global__ void zero_kernel(float4* agg4, float* deg, int n4, int nd) {
    int i = blockIdx.x * blockDim.x + threadIdx.x;
    if (i < n4) agg4[i] = make_float4(0.f, 0.f, 0.f, 0.f);
    if (i < nd) deg[i] = 0.f;
}

// One warp per edge: 32 lanes x float4 = 128 floats.
__global__ void scatter_kernel(const int* __restrict__ ei,
                               const float* __restrict__ emb,
                               float* __restrict__ agg,
                               float* __restrict__ deg,
                               int E) {
    int warp  = (blockIdx.x * blockDim.x + threadIdx.x) >> 5;
    int lane  = threadIdx.x & 31;
    int nwarp = (gridDim.x * blockDim.x) >> 5;
    for (int e = warp; e < E; e += nwarp) {
        int src = __ldg(&ei[e]);
        int dst = __ldg(&ei[E + e]);
        float4 v = *(const float4*)(emb + (size_t)src * HID + lane * 4);
        // sm_90+ vector reduction (RED.ADD.v4.f32, no return value)
        atomicAdd((float4*)(agg + (size_t)dst * HID + lane * 4), v);
        if (lane == 0) atomicAdd(&deg[dst], 1.0f);
    }
}

__global__ void finalize_kernel(float4* agg4, const float* __restrict__ deg, int M) {
    int i = blockIdx.x * blockDim.x + threadIdx.x;   // over M*32 float4s
    int total = M * (HID / 4);
    if (i >= total) return;
    int m = i >> 5;                                  // HID/4 = 32 float4 per row
    float inv = 1.0f / fmaxf(deg[m], 1.0f);
    float4 v = agg4[i];
    v.x *= inv; v.y *= inv; v.z *= inv; v.w *= inv;
    agg4[i] = v;
}

// ---------------------------------------------------------------------------
// Main SGEMM: C[M,128] = epi(A[M,K_DIM] @ W[K_DIM,128] + bias)
// Block tile 128x128, TK=16, 256 threads, 8x8 per thread.
// EPI: 0 = none, 1 = relu, 2 = LINKX combine (reads hx/ha from A = g_cat)
// ---------------------------------------------------------------------------
template <int K_DIM, int EPI>
__global__ __launch_bounds__(256, 2)
void gemm_k(const float* __restrict__ A,
            const float* __restrict__ W,
            const float* __restrict__ bias,
            float* __restrict__ C, int ldc, int coff, int M) {
    __shared__ float As[16][128];   // transposed: As[k][m]
    __shared__ float Bs[16][128];   // Bs[k][n]

    const int tid = threadIdx.x;
    const int bm  = blockIdx.x * 128;
    const int ty  = tid >> 4;       // 0..15
    const int tx  = tid & 15;       // 0..15
    const int rm  = ty * 8;
    const int cn  = tx * 8;

    float acc[8][8];
#pragma unroll
    for (int i = 0; i < 8; ++i)
#pragma unroll
        for (int j = 0; j < 8; ++j) acc[i][j] = 0.f;

    for (int k0 = 0; k0 < K_DIM; k0 += 16) {
        // Load A tile (128 rows x 16 k) transposed into As[k][m]
#pragma unroll
        for (int u0 = 0; u0 < 512; u0 += 256) {
            int u   = u0 + tid;
            int row = u >> 2;
            int kq  = (u & 3) * 4;
            int gr  = bm + row;
            float4 v = make_float4(0.f, 0.f, 0.f, 0.f);
            if (gr < M) v = *(const float4*)&A[(size_t)gr * K_DIM + k0 + kq];
            As[kq + 0][row] = v.x;
            As[kq + 1][row] = v.y;
            As[kq + 2][row] = v.z;
            As[kq + 3][row] = v.w;
        }
        // Load B tile (16 k x 128 n)
#pragma unroll
        for (int u0 = 0; u0 < 512; u0 += 256) {
            int u  = u0 + tid;
            int kr = u >> 5;
            int nq = (u & 31) * 4;
            *(float4*)&Bs[kr][nq] = *(const float4*)&W[(size_t)(k0 + kr) * 128 + nq];
        }
        __syncthreads();

#pragma unroll
        for (int kk = 0; kk < 16; ++kk) {
            float4 a0 = *(const float4*)&As[kk][rm];
            float4 a1 = *(const float4*)&As[kk][rm + 4];
            float4 b0 = *(const float4*)&Bs[kk][cn];
            float4 b1 = *(const float4*)&Bs[kk][cn + 4];
            float a[8] = {a0.x, a0.y, a0.z, a0.w, a1.x, a1.y, a1.z, a1.w};
            float b[8] = {b0.x, b0.y, b0.z, b0.w, b1.x, b1.y, b1.z, b1.w};
#pragma unroll
            for (int i = 0; i < 8; ++i)
#pragma unroll
                for (int j = 0; j < 8; ++j)
                    acc[i][j] = fmaf(a[i], b[j], acc[i][j]);
        }
        __syncthreads();
    }

    float bb[8];
#pragma unroll
    for (int j = 0; j < 8; ++j) bb[j] = bias[cn + j];

#pragma unroll
    for (int i = 0; i < 8; ++i) {
        int r = bm + rm + i;
        if (r >= M) break;
        float o[8];
#pragma unroll
        for (int j = 0; j < 8; ++j) {
            float z = acc[i][j] + bb[j];
            if (EPI == 1) z = fmaxf(z, 0.f);
            o[j] = z;
        }
        if (EPI == 2) {
            // out = relu(relu(z) + hx + ha); A is g_cat [M,256]: hx=cols 0..127, ha=128..255
            float4 hx0 = *(const float4*)&A[(size_t)r * 256 + cn];
            float4 hx1 = *(const float4*)&A[(size_t)r * 256 + cn + 4];
            float4 ha0 = *(const float4*)&A[(size_t)r * 256 + 128 + cn];
            float4 ha1 = *(const float4*)&A[(size_t)r * 256 + 128 + cn + 4];
            float hx[8] = {hx0.x, hx0.y, hx0.z, hx0.w, hx1.x, hx1.y, hx1.z, hx1.w};
            float ha[8] = {ha0.x, ha0.y, ha0.z, ha0.w, ha1.x, ha1.y, ha1.z, ha1.w};
#pragma unroll
            for (int j = 0; j < 8; ++j)
                o[j] = fmaxf(fmaxf(o[j], 0.f) + hx[j] + ha[j], 0.f);
        }
        float* cp = &C[(size_t)r * ldc + coff + cn];
        *(float4*)(cp)     = make_float4(o[0], o[1], o[2], o[3]);
        *(float4*)(cp + 4) = make_float4(o[4], o[5], o[6], o[7]);
    }
}

// ---------------------------------------------------------------------------
// Classifier GEMM: out[M,40] = A[M,128] @ W[128,40] + bias
// Block tile 128x40, TK=16, 128 threads, 8x5 per thread.
// ---------------------------------------------------------------------------
__global__ __launch_bounds__(128)
void gemm_out(const float* __restrict__ A,
              const float* __restrict__ W,
              const float* __restrict__ bias,
              float* __restrict__ out, int M) {
    __shared__ float As[16][128];   // As[k][m]
    __shared__ float Ws[16 * 40];   // Ws[k*40 + c]

    const int tid = threadIdx.x;
    const int bm  = blockIdx.x * 128;
    const int ty  = tid >> 3;       // 0..15
    const int tx  = tid & 7;        // 0..7
    const int rm  = ty * 8;
    const int cn  = tx * 5;

    float acc[8][5];
#pragma unroll
    for (int i = 0; i < 8; ++i)
#pragma unroll
        for (int j = 0; j < 5; ++j) acc[i][j] = 0.f;

    for (int k0 = 0; k0 < 128; k0 += 16) {
#pragma unroll
        for (int u0 = 0; u0 < 512; u0 += 128) {
            int u   = u0 + tid;
            int row = u >> 2;
            int kq  = (u & 3) * 4;
            int gr  = bm + row;
            float4 v = make_float4(0.f, 0.f, 0.f, 0.f);
            if (gr < M) v = *(const float4*)&A[(size_t)gr * 128 + k0 + kq];
            As[kq + 0][row] = v.x;
            As[kq + 1][row] = v.y;
            As[kq + 2][row] = v.z;
            As[kq + 3][row] = v.w;
        }
        for (int u = tid; u < 16 * 40; u += 128) {
            int kr = u / 40, c = u % 40;
            Ws[u] = W[(size_t)(k0 + kr) * 40 + c];
        }
        __syncthreads();

#pragma unroll
        for (int kk = 0; kk < 16; ++kk) {
            float4 a0 = *(const float4*)&As[kk][rm];
            float4 a1 = *(const float4*)&As[kk][rm + 4];
            float a[8] = {a0.x, a0.y, a0.z, a0.w, a1.x, a1.y, a1.z, a1.w};
            float w[5];
#pragma unroll
            for (int j = 0; j < 5; ++j) w[j] = Ws[kk * 40 + cn + j];
#pragma unroll
            for (int i = 0; i < 8; ++i)
#pragma unroll
                for (int j = 0; j < 5; ++j)
                    acc[i][j] = fmaf(a[i], w[j], acc[i][j]);
        }
        __syncthreads();
    }

    float bb[5];
#pragma unroll
    for (int j = 0; j < 5; ++j) bb[j] = bias[cn + j];
#pragma unroll
    for (int i = 0; i < 8; ++i) {
        int r = bm + rm + i;
        if (r >= M) break;
#pragma unroll
        for (int j = 0; j < 5; ++j)
            out[(size_t)r * 40 + cn + j] = acc[i][j] + bb[j];
    }
}

// ---------------------------------------------------------------------------
extern "C" void kernel_launch(void* const* d_in, const int* in_sizes, int n_in,
                              void* d_out, int out_size) {
    const float* x   = (const float*)d_in[0];
    const int*   ei  = (const int*)  d_in[1];
    const float* emb = (const float*)d_in[2];
    const float* wx1 = (const float*)d_in[3];
    const float* bx1 = (const float*)d_in[4];
    const float* wx2 = (const float*)d_in[5];
    const float* bx2 = (const float*)d_in[6];
    const float* wa1 = (const float*)d_in[7];
    const float* ba1 = (const float*)d_in[8];
    const float* wa2 = (const float*)d_in[9];
    const float* ba2 = (const float*)d_in[10];
    const float* ww1 = (const float*)d_in[11];
    const float* bw1 = (const float*)d_in[12];
    const float* wc  = (const float*)d_in[13];
    const float* bc  = (const float*)d_in[14];
    float* out = (float*)d_out;

    const int M = in_sizes[0] / INDIM;   // 100000
    const int E = in_sizes[1] / 2;       // 1600000

    float *agg, *deg, *hid, *cat;
    cudaGetSymbolAddress((void**)&agg, g_agg);
    cudaGetSymbolAddress((void**)&deg, g_deg);
    cudaGetSymbolAddress((void**)&hid, g_hid);
    cudaGetSymbolAddress((void**)&cat, g_cat);

    const int n4 = M * (HID / 4);
    zero_kernel<<<(n4 + 255) / 256, 256>>>((float4*)agg, deg, n4, M);

    // 8 edges per block (one warp each)
    scatter_kernel<<<(E + 7) / 8, 256>>>(ei, emb, agg, deg, E);
    finalize_kernel<<<(n4 + 255) / 256, 256>>>((float4*)agg, deg, M);

    const int gb = (M + 127) / 128;
    // x branch: hid = relu(x@wx1+b); cat[:,0:128] = hid@wx2+b  (hx)
    gemm_k<INDIM, 1><<<gb, 256>>>(x,   wx1, bx1, hid, 128, 0,   M);
    gemm_k<HID,   0><<<gb, 256>>>(hid, wx2, bx2, cat, 256, 0,   M);
    // adj branch: hid = relu(ha_raw@wa1+b); cat[:,128:256] = hid@wa2+b  (ha)
    gemm_k<HID,   1><<<gb, 256>>>(agg, wa1, ba1, hid, 128, 0,   M);
    gemm_k<HID,   0><<<gb, 256>>>(hid, wa2, ba2, cat, 256, 128, M);
    // combine: hid = relu(relu(cat@ww1+b) + hx + ha)
    gemm_k<2*HID, 2><<<gb, 256>>>(cat, ww1, bw1, hid, 128, 0,   M);
    // classifier
    gemm_out<<<gb, 128>>>(hid, wc, bc, out, M);
}